// round 6
// baseline (speedup 1.0000x reference)
#include <cuda_runtime.h>
#include <math.h>

#define NN 100000
#define EE 1600000
#define CC 32
#define SCAN_T 512
#define NB ((NN + SCAN_T - 1) / SCAN_T)   /* 196 */

// ---------------- scratch (static device globals; no allocation) -------------
__device__ float g_deg[NN];
// zero-buffer: [0, NN) = in-degree counts, [NN, NN+512) = scan lookback state
__device__ __align__(8) int g_zbuf[NN + 512];
__device__ int   g_row[NN + 1];
__device__ int   g_cur[NN];
__device__ int2  g_csr[EE];          // (src, coef bits), grouped by dst
__device__ float g_px2[NN * CC];     // gate-2 x-side preactivation (incl. bias)
__device__ float g_z[NN * CC];
__device__ float g_hr[NN * CC];

// ---------------- f32x2 packed-FMA helpers -----------------------------------
__device__ __forceinline__ unsigned long long pack2(float a, float b) {
    unsigned long long v;
    asm("mov.b64 %0, {%1, %2};" : "=l"(v) : "f"(a), "f"(b));
    return v;
}
__device__ __forceinline__ float2 unpack2(unsigned long long v) {
    float2 r;
    asm("mov.b64 {%0, %1}, %2;" : "=f"(r.x), "=f"(r.y) : "l"(v));
    return r;
}
__device__ __forceinline__ void fma2(unsigned long long& acc, float2 w,
                                     float s0, float s1) {
    unsigned long long wv = pack2(w.x, w.y);
    unsigned long long sv = pack2(s0, s1);
    asm("fma.rn.f32x2 %0, %1, %2, %3;" : "=l"(acc) : "l"(wv), "l"(sv), "l"(acc));
}

// ---------------- k_deg_hist: 4 edges per thread ------------------------------
__global__ void k_deg_hist(const int* __restrict__ ei, const float* __restrict__ w) {
    int t = blockIdx.x * blockDim.x + threadIdx.x;
    if (t >= EE / 4) return;
    int4 s = ((const int4*)ei)[t];
    int4 d = ((const int4*)(ei + EE))[t];
    float4 wv = ((const float4*)w)[t];
    atomicAdd(&g_deg[s.x], wv.x);
    atomicAdd(&g_deg[s.y], wv.y);
    atomicAdd(&g_deg[s.z], wv.z);
    atomicAdd(&g_deg[s.w], wv.w);
    atomicAdd(&g_zbuf[d.x], 1);
    atomicAdd(&g_zbuf[d.y], 1);
    atomicAdd(&g_zbuf[d.z], 1);
    atomicAdd(&g_zbuf[d.w], 1);
}

// ---------------- k_scan: single-pass exclusive scan, warp-parallel lookback --
// state[b]: bits[63:32] flag (0=empty, 1=aggregate, 2=inclusive), bits[31:0] value
__global__ void k_scan() {
    __shared__ int s[SCAN_T];
    __shared__ int sPrefix;
    unsigned long long* state = (unsigned long long*)(g_zbuf + NN);
    int t = threadIdx.x;
    int b = blockIdx.x;
    int i = b * SCAN_T + t;
    int v = (i < NN) ? g_zbuf[i] : 0;
    s[t] = v;
    __syncthreads();
    for (int off = 1; off < SCAN_T; off <<= 1) {
        int a = (t >= off) ? s[t - off] : 0;
        __syncthreads();
        s[t] += a;
        __syncthreads();
    }
    int total = s[SCAN_T - 1];

    if (b == 0) {
        if (t == 0) { atomicExch(&state[0], (2ULL << 32) | (unsigned)total); sPrefix = 0; }
    } else if (t < 32) {
        if (t == 0) atomicExch(&state[b], (1ULL << 32) | (unsigned)total);
        int prefix = 0;
        int j = b - 1 - t;           // lane t polls block j (lane 0 = nearest)
        for (;;) {
            unsigned flag = 0; int val = 0;
            if (j >= 0) {
                unsigned long long sj;
                do { sj = atomicOr(&state[j], 0ULL); flag = (unsigned)(sj >> 32); }
                while (flag == 0u);
                val = (int)(unsigned)sj;
            }
            unsigned incmask = __ballot_sync(0xffffffffu, (j >= 0) && flag == 2u);
            if (incmask) {
                int k = __ffs(incmask) - 1;   // nearest inclusive
                if (t > k) val = 0;
            }
#pragma unroll
            for (int off = 16; off > 0; off >>= 1)
                val += __shfl_xor_sync(0xffffffffu, val, off);
            prefix += val;
            if (incmask) break;
            j -= 32;
        }
        if (t == 0) {
            atomicExch(&state[b], (2ULL << 32) | (unsigned)(prefix + total));
            sPrefix = prefix;
        }
    }
    __syncthreads();
    int pre = (b == 0) ? 0 : sPrefix;
    if (i < NN) {
        int rs = pre + s[t] - v;   // exclusive
        g_row[i] = rs;
        g_cur[i] = rs;
    }
    if (b == 0 && t == 0) g_row[NN] = EE;
}

// ---------------- k_place: 4 edges per thread ---------------------------------
__global__ void k_place(const int* __restrict__ ei, const float* __restrict__ w) {
    int t = blockIdx.x * blockDim.x + threadIdx.x;
    if (t >= EE / 4) return;
    int4 s = ((const int4*)ei)[t];
    int4 d = ((const int4*)(ei + EE))[t];
    float4 wv = ((const float4*)w)[t];
    float ds0 = g_deg[s.x], ds1 = g_deg[s.y], ds2 = g_deg[s.z], ds3 = g_deg[s.w];
    float dd0 = g_deg[d.x], dd1 = g_deg[d.y], dd2 = g_deg[d.z], dd3 = g_deg[d.w];
    float c0 = -((ds0 > 0.f ? rsqrtf(ds0) : 0.f) * wv.x * (dd0 > 0.f ? rsqrtf(dd0) : 0.f));
    float c1 = -((ds1 > 0.f ? rsqrtf(ds1) : 0.f) * wv.y * (dd1 > 0.f ? rsqrtf(dd1) : 0.f));
    float c2 = -((ds2 > 0.f ? rsqrtf(ds2) : 0.f) * wv.z * (dd2 > 0.f ? rsqrtf(dd2) : 0.f));
    float c3 = -((ds3 > 0.f ? rsqrtf(ds3) : 0.f) * wv.w * (dd3 > 0.f ? rsqrtf(dd3) : 0.f));
    int p0 = atomicAdd(&g_cur[d.x], 1);
    int p1 = atomicAdd(&g_cur[d.y], 1);
    int p2 = atomicAdd(&g_cur[d.z], 1);
    int p3 = atomicAdd(&g_cur[d.w], 1);
    g_csr[p0] = make_int2(s.x, __float_as_int(c0));
    g_csr[p1] = make_int2(s.y, __float_as_int(c1));
    g_csr[p2] = make_int2(s.z, __float_as_int(c2));
    g_csr[p3] = make_int2(s.w, __float_as_int(c3));
}

// ---------------- gathers (unroll 8 for MLP) -----------------------------------
__device__ __forceinline__ void gather2(int node, int lane,
                                        const float* __restrict__ a,
                                        const float* __restrict__ b,
                                        float& ra, float& rb) {
    int beg = g_row[node], end = g_row[node + 1];
    float sa = 0.0f, sb = 0.0f;
    int e = beg;
    for (; e + 8 <= end; e += 8) {
        int2 t0 = g_csr[e],     t1 = g_csr[e + 1], t2 = g_csr[e + 2], t3 = g_csr[e + 3];
        int2 t4 = g_csr[e + 4], t5 = g_csr[e + 5], t6 = g_csr[e + 6], t7 = g_csr[e + 7];
        float a0 = a[t0.x * CC + lane], a1 = a[t1.x * CC + lane];
        float a2 = a[t2.x * CC + lane], a3 = a[t3.x * CC + lane];
        float a4 = a[t4.x * CC + lane], a5 = a[t5.x * CC + lane];
        float a6 = a[t6.x * CC + lane], a7 = a[t7.x * CC + lane];
        float b0 = b[t0.x * CC + lane], b1 = b[t1.x * CC + lane];
        float b2 = b[t2.x * CC + lane], b3 = b[t3.x * CC + lane];
        float b4 = b[t4.x * CC + lane], b5 = b[t5.x * CC + lane];
        float b6 = b[t6.x * CC + lane], b7 = b[t7.x * CC + lane];
        sa += __int_as_float(t0.y) * a0 + __int_as_float(t1.y) * a1
            + __int_as_float(t2.y) * a2 + __int_as_float(t3.y) * a3
            + __int_as_float(t4.y) * a4 + __int_as_float(t5.y) * a5
            + __int_as_float(t6.y) * a6 + __int_as_float(t7.y) * a7;
        sb += __int_as_float(t0.y) * b0 + __int_as_float(t1.y) * b1
            + __int_as_float(t2.y) * b2 + __int_as_float(t3.y) * b3
            + __int_as_float(t4.y) * b4 + __int_as_float(t5.y) * b5
            + __int_as_float(t6.y) * b6 + __int_as_float(t7.y) * b7;
    }
    for (; e < end; e++) {
        int2 t = g_csr[e];
        float c = __int_as_float(t.y);
        sa += c * a[t.x * CC + lane];
        sb += c * b[t.x * CC + lane];
    }
    ra = sa; rb = sb;
}

__device__ __forceinline__ void gather1(int node, int lane,
                                        const float* __restrict__ a, float& ra) {
    int beg = g_row[node], end = g_row[node + 1];
    float sa = 0.0f;
    int e = beg;
    for (; e + 8 <= end; e += 8) {
        int2 t0 = g_csr[e],     t1 = g_csr[e + 1], t2 = g_csr[e + 2], t3 = g_csr[e + 3];
        int2 t4 = g_csr[e + 4], t5 = g_csr[e + 5], t6 = g_csr[e + 6], t7 = g_csr[e + 7];
        float a0 = a[t0.x * CC + lane], a1 = a[t1.x * CC + lane];
        float a2 = a[t2.x * CC + lane], a3 = a[t3.x * CC + lane];
        float a4 = a[t4.x * CC + lane], a5 = a[t5.x * CC + lane];
        float a6 = a[t6.x * CC + lane], a7 = a[t7.x * CC + lane];
        sa += __int_as_float(t0.y) * a0 + __int_as_float(t1.y) * a1
            + __int_as_float(t2.y) * a2 + __int_as_float(t3.y) * a3
            + __int_as_float(t4.y) * a4 + __int_as_float(t5.y) * a5
            + __int_as_float(t6.y) * a6 + __int_as_float(t7.y) * a7;
    }
    for (; e < end; e++) {
        int2 t = g_csr[e];
        sa += __int_as_float(t.y) * a[t.x * CC + lane];
    }
    ra = sa;
}

// ---------------- k_gates: gather(x,h) + gates z,r + px2 (8 nodes/warp) -------
// k-pair packing: every fma2 reads weight pair (w_k, w_k+1) from smem and a
// natural (s_k, s_k+1) register pair out of an LDS.128 -> zero MOV overhead.
__global__ void __launch_bounds__(256, 2) k_gates(
        const float* __restrict__ x, const float* __restrict__ h,
        const float* __restrict__ Wx, const float* __restrict__ bx,
        const float* __restrict__ Wh, const float* __restrict__ bh) {
    extern __shared__ float2 dynw[];
    float2* sZ0 = dynw;            // z: Wx[0,0] k-pairs
    float2* sZ1 = dynw + 512;      // z: Wx[0,1]
    float2* sZ2 = dynw + 1024;     // z: Wh[0,0]
    float2* sZ3 = dynw + 1536;     // z: Wh[0,1]
    float2* sR0 = dynw + 2048;     // r: Wx[1,0]
    float2* sR1 = dynw + 2560;     // r: Wx[1,1]
    float2* sR2 = dynw + 3072;     // r: Wh[1,0]
    float2* sR3 = dynw + 3584;     // r: Wh[1,1]
    float2* sP0 = dynw + 4096;     // px2: Wx[2,0]
    float2* sP1 = dynw + 4608;     // px2: Wx[2,1]
    __shared__ __align__(16) float sIn[8 * 8 * 4 * 32];  // 32KB

    int tid = threadIdx.x;
    for (int i = tid; i < 512; i += blockDim.x) {
        int t = i >> 5, c = i & 31;
        int o = t * 64 + c;
        sZ0[i] = make_float2(Wx[o],        Wx[o + 32]);
        sZ1[i] = make_float2(Wx[1024 + o], Wx[1024 + o + 32]);
        sZ2[i] = make_float2(Wh[o],        Wh[o + 32]);
        sZ3[i] = make_float2(Wh[1024 + o], Wh[1024 + o + 32]);
        sR0[i] = make_float2(Wx[2048 + o], Wx[2048 + o + 32]);
        sR1[i] = make_float2(Wx[3072 + o], Wx[3072 + o + 32]);
        sR2[i] = make_float2(Wh[2048 + o], Wh[2048 + o + 32]);
        sR3[i] = make_float2(Wh[3072 + o], Wh[3072 + o + 32]);
        sP0[i] = make_float2(Wx[4096 + o], Wx[4096 + o + 32]);
        sP1[i] = make_float2(Wx[5120 + o], Wx[5120 + o + 32]);
    }
    __syncthreads();

    int lane = tid & 31;
    int warp = tid >> 5;
    float bz = bx[lane] + bh[lane];
    float br = bx[32 + lane] + bh[32 + lane];
    float b2 = bx[64 + lane] + bh[64 + lane];

    int gw = blockIdx.x * 8 + warp;
    int stride = gridDim.x * 8 * 8;
    float* stage = &sIn[warp * 1024];

    for (int nb = gw * 8; nb < NN; nb += stride) {
        // ---- gather phase: stage x, aggx, h, aggh for up to 8 nodes ----
#pragma unroll 1
        for (int i = 0; i < 8; i++) {
            int node = nb + i;
            float xv = 0.f, hvv = 0.f, ax = 0.f, ah = 0.f;
            if (node < NN) {
                int base = node * CC + lane;
                xv = x[base];
                hvv = h[base];
                gather2(node, lane, x, h, ax, ah);
            }
            stage[i * 128 +  0 + lane] = xv;
            stage[i * 128 + 32 + lane] = ax;
            stage[i * 128 + 64 + lane] = hvv;
            stage[i * 128 + 96 + lane] = ah;
        }
        __syncwarp();

        unsigned long long accz[8], accr[8], accp[8];
#pragma unroll
        for (int i = 0; i < 8; i++) {
            accz[i] = pack2(bz, 0.f);
            accr[i] = pack2(br, 0.f);
            accp[i] = pack2(b2, 0.f);
        }
        const float4* st4 = (const float4*)stage;

#pragma unroll 1
        for (int q = 0; q < 8; q++) {
            int r0 = (2 * q) * 32 + lane, r1 = (2 * q + 1) * 32 + lane;
            float2 z0a = sZ0[r0], z0b = sZ0[r1], z1a = sZ1[r0], z1b = sZ1[r1];
            float2 z2a = sZ2[r0], z2b = sZ2[r1], z3a = sZ3[r0], z3b = sZ3[r1];
            float2 q0a = sR0[r0], q0b = sR0[r1], q1a = sR1[r0], q1b = sR1[r1];
            float2 q2a = sR2[r0], q2b = sR2[r1], q3a = sR3[r0], q3b = sR3[r1];
            float2 p0a = sP0[r0], p0b = sP0[r1], p1a = sP1[r0], p1b = sP1[r1];
#pragma unroll
            for (int i = 0; i < 8; i++) {
                float4 vx = st4[i * 32 +  0 + q];
                float4 va = st4[i * 32 +  8 + q];
                float4 vh = st4[i * 32 + 16 + q];
                float4 vr = st4[i * 32 + 24 + q];
                fma2(accz[i], z0a, vx.x, vx.y); fma2(accz[i], z0b, vx.z, vx.w);
                fma2(accz[i], z1a, va.x, va.y); fma2(accz[i], z1b, va.z, va.w);
                fma2(accz[i], z2a, vh.x, vh.y); fma2(accz[i], z2b, vh.z, vh.w);
                fma2(accz[i], z3a, vr.x, vr.y); fma2(accz[i], z3b, vr.z, vr.w);
                fma2(accr[i], q0a, vx.x, vx.y); fma2(accr[i], q0b, vx.z, vx.w);
                fma2(accr[i], q1a, va.x, va.y); fma2(accr[i], q1b, va.z, va.w);
                fma2(accr[i], q2a, vh.x, vh.y); fma2(accr[i], q2b, vh.z, vh.w);
                fma2(accr[i], q3a, vr.x, vr.y); fma2(accr[i], q3b, vr.z, vr.w);
                fma2(accp[i], p0a, vx.x, vx.y); fma2(accp[i], p0b, vx.z, vx.w);
                fma2(accp[i], p1a, va.x, va.y); fma2(accp[i], p1b, va.z, va.w);
            }
        }

#pragma unroll 1
        for (int i = 0; i < 8; i++) {
            int node = nb + i;
            if (node >= NN) break;
            float2 az = unpack2(accz[i]);
            float2 ar = unpack2(accr[i]);
            float2 ap = unpack2(accp[i]);
            float z = 1.0f / (1.0f + __expf(-(az.x + az.y)));
            float r = 1.0f / (1.0f + __expf(-(ar.x + ar.y)));
            int base = node * CC + lane;
            float hvv = stage[i * 128 + 64 + lane];
            g_z[base] = z;
            g_hr[base] = hvv * r;
            g_px2[base] = ap.x + ap.y;
        }
        __syncwarp();
    }
}

// ---------------- k_final: gather(hr) + h_tilde + h_new + head (8 nodes/warp) -
__global__ void __launch_bounds__(256) k_final(
        const float* __restrict__ h,
        const float* __restrict__ Wh,
        const float* __restrict__ Wl, const float* __restrict__ bl,
        float* __restrict__ out) {
    extern __shared__ float2 dynw[];
    float2* sQ0 = dynw;          // Wh[2,0] k-pairs
    float2* sQ1 = dynw + 512;    // Wh[2,1] k-pairs
    __shared__ __align__(16) float sIn[8 * 8 * 2 * 32];
    __shared__ float sWl[32];

    int tid = threadIdx.x;
    for (int i = tid; i < 512; i += blockDim.x) {
        int t = i >> 5, c = i & 31;
        int o = t * 64 + c;
        sQ0[i] = make_float2(Wh[4096 + o], Wh[4096 + o + 32]);
        sQ1[i] = make_float2(Wh[5120 + o], Wh[5120 + o + 32]);
    }
    if (tid < 32) sWl[tid] = Wl[tid];
    __syncthreads();

    int lane = tid & 31;
    int warp = tid >> 5;
    float blv = bl[0];

    int gw = blockIdx.x * 8 + warp;
    int stride = gridDim.x * 8 * 8;
    float* stage = &sIn[warp * 512];

    for (int nb = gw * 8; nb < NN; nb += stride) {
        float px2r[8];
#pragma unroll 1
        for (int i = 0; i < 8; i++) {
            int node = nb + i;
            float hrv = 0.f, ahr = 0.f, px = 0.f;
            if (node < NN) {
                int base = node * CC + lane;
                hrv = g_hr[base];
                px = g_px2[base];
                gather1(node, lane, g_hr, ahr);
            }
            px2r[i] = px;
            stage[i * 64 +  0 + lane] = hrv;
            stage[i * 64 + 32 + lane] = ahr;
        }
        __syncwarp();

        unsigned long long acc[8];
#pragma unroll
        for (int i = 0; i < 8; i++) acc[i] = pack2(px2r[i], 0.f);
        const float4* st4 = (const float4*)stage;

#pragma unroll 1
        for (int q = 0; q < 8; q++) {
            int r0 = (2 * q) * 32 + lane, r1 = (2 * q + 1) * 32 + lane;
            float2 w0a = sQ0[r0], w0b = sQ0[r1];
            float2 w1a = sQ1[r0], w1b = sQ1[r1];
#pragma unroll
            for (int i = 0; i < 8; i++) {
                float4 vh = st4[i * 16 + 0 + q];
                float4 vr = st4[i * 16 + 8 + q];
                fma2(acc[i], w0a, vh.x, vh.y); fma2(acc[i], w0b, vh.z, vh.w);
                fma2(acc[i], w1a, vr.x, vr.y); fma2(acc[i], w1b, vr.z, vr.w);
            }
        }

#pragma unroll 1
        for (int i = 0; i < 8; i++) {
            int node = nb + i;
            if (node >= NN) break;
            float2 a2 = unpack2(acc[i]);
            float ht = tanhf(a2.x + a2.y);
            int base = node * CC + lane;
            float zv = g_z[base];
            float hvv = h[base];
            float hn = zv * hvv + (1.0f - zv) * ht;

            out[NN + base] = hn;

            float rl = fmaxf(hn, 0.0f) * sWl[lane];
#pragma unroll
            for (int off = 16; off > 0; off >>= 1)
                rl += __shfl_xor_sync(0xffffffffu, rl, off);
            if (lane == 0) {
                float s = rl + blv;
                out[node] = log1pf(__expf(-fabsf(s))) + fmaxf(s, 0.0f);
            }
        }
        __syncwarp();
    }
}

// ---------------- launch ------------------------------------------------------
extern "C" void kernel_launch(void* const* d_in, const int* in_sizes, int n_in,
                              void* d_out, int out_size) {
    const float* x  = (const float*)d_in[0];
    const int*   ei = (const int*)d_in[1];
    const float* w  = (const float*)d_in[2];
    const float* h  = (const float*)d_in[3];
    const float* Wx = (const float*)d_in[4];
    const float* bx = (const float*)d_in[5];
    const float* Wh = (const float*)d_in[6];
    const float* bh = (const float*)d_in[7];
    const float* Wl = (const float*)d_in[8];
    const float* bl = (const float*)d_in[9];
    float* out = (float*)d_out;

    (void)in_sizes; (void)n_in; (void)out_size;

    cudaFuncSetAttribute(k_gates, cudaFuncAttributeMaxDynamicSharedMemorySize, 5120 * 8);
    cudaFuncSetAttribute(k_final, cudaFuncAttributeMaxDynamicSharedMemorySize, 1024 * 8);

    void* p_deg = nullptr; cudaGetSymbolAddress(&p_deg, g_deg);
    void* p_zb  = nullptr; cudaGetSymbolAddress(&p_zb, g_zbuf);
    cudaMemsetAsync(p_deg, 0, NN * sizeof(float));
    cudaMemsetAsync(p_zb, 0, (NN + 512) * sizeof(int));

    k_deg_hist<<<(EE / 4 + 255) / 256, 256>>>(ei, w);
    k_scan<<<NB, SCAN_T>>>();
    k_place<<<(EE / 4 + 255) / 256, 256>>>(ei, w);
    k_gates<<<296, 256, 5120 * 8>>>(x, h, Wx, bx, Wh, bh);
    k_final<<<592, 256, 1024 * 8>>>(h, Wh, Wl, bl, out);
}

// round 7
// speedup vs baseline: 1.1270x; 1.1270x over previous
#include <cuda_runtime.h>
#include <math.h>

#define NN 100000
#define EE 1600000
#define CC 32
#define SCAN_T 512
#define NB ((NN + SCAN_T - 1) / SCAN_T)   /* 196 */

// ---------------- scratch (static device globals; no allocation) -------------
__device__ float g_deg[NN];
// zero-buffer: [0, NN) = in-degree counts, [NN, NN+512) = scan lookback state
__device__ __align__(8) int g_zbuf[NN + 512];
__device__ int   g_row[NN + 1];
__device__ int   g_cur[NN];
__device__ int2  g_csr[EE];          // (src, coef bits), grouped by dst
__device__ float g_px2[NN * CC];     // gate-2 x-side preactivation (incl. bias)
__device__ float g_z[NN * CC];
__device__ float g_hr[NN * CC];

// ---------------- f32x2 packed-FMA helpers -----------------------------------
__device__ __forceinline__ unsigned long long pack2(float a, float b) {
    unsigned long long v;
    asm("mov.b64 %0, {%1, %2};" : "=l"(v) : "f"(a), "f"(b));
    return v;
}
__device__ __forceinline__ float2 unpack2(unsigned long long v) {
    float2 r;
    asm("mov.b64 {%0, %1}, %2;" : "=f"(r.x), "=f"(r.y) : "l"(v));
    return r;
}
__device__ __forceinline__ void fma2(unsigned long long& acc, float2 w,
                                     float s0, float s1) {
    unsigned long long wv = pack2(w.x, w.y);
    unsigned long long sv = pack2(s0, s1);
    asm("fma.rn.f32x2 %0, %1, %2, %3;" : "=l"(acc) : "l"(wv), "l"(sv), "l"(acc));
}

// ---------------- k_deg_hist: 4 edges per thread ------------------------------
__global__ void k_deg_hist(const int* __restrict__ ei, const float* __restrict__ w) {
    int t = blockIdx.x * blockDim.x + threadIdx.x;
    if (t >= EE / 4) return;
    int4 s = ((const int4*)ei)[t];
    int4 d = ((const int4*)(ei + EE))[t];
    float4 wv = ((const float4*)w)[t];
    atomicAdd(&g_deg[s.x], wv.x);
    atomicAdd(&g_deg[s.y], wv.y);
    atomicAdd(&g_deg[s.z], wv.z);
    atomicAdd(&g_deg[s.w], wv.w);
    atomicAdd(&g_zbuf[d.x], 1);
    atomicAdd(&g_zbuf[d.y], 1);
    atomicAdd(&g_zbuf[d.z], 1);
    atomicAdd(&g_zbuf[d.w], 1);
}

// ---------------- k_scan: single-pass exclusive scan, warp-parallel lookback --
// state[b]: bits[63:32] flag (0=empty, 1=aggregate, 2=inclusive), bits[31:0] value
__global__ void k_scan() {
    __shared__ int s[SCAN_T];
    __shared__ int sPrefix;
    unsigned long long* state = (unsigned long long*)(g_zbuf + NN);
    int t = threadIdx.x;
    int b = blockIdx.x;
    int i = b * SCAN_T + t;
    int v = (i < NN) ? g_zbuf[i] : 0;
    s[t] = v;
    __syncthreads();
    for (int off = 1; off < SCAN_T; off <<= 1) {
        int a = (t >= off) ? s[t - off] : 0;
        __syncthreads();
        s[t] += a;
        __syncthreads();
    }
    int total = s[SCAN_T - 1];

    if (b == 0) {
        if (t == 0) { atomicExch(&state[0], (2ULL << 32) | (unsigned)total); sPrefix = 0; }
    } else if (t < 32) {
        if (t == 0) atomicExch(&state[b], (1ULL << 32) | (unsigned)total);
        int prefix = 0;
        int j = b - 1 - t;           // lane t polls block j (lane 0 = nearest)
        for (;;) {
            unsigned flag = 0; int val = 0;
            if (j >= 0) {
                unsigned long long sj;
                do { sj = atomicOr(&state[j], 0ULL); flag = (unsigned)(sj >> 32); }
                while (flag == 0u);
                val = (int)(unsigned)sj;
            }
            unsigned incmask = __ballot_sync(0xffffffffu, (j >= 0) && flag == 2u);
            if (incmask) {
                int k = __ffs(incmask) - 1;   // nearest inclusive
                if (t > k) val = 0;
            }
#pragma unroll
            for (int off = 16; off > 0; off >>= 1)
                val += __shfl_xor_sync(0xffffffffu, val, off);
            prefix += val;
            if (incmask) break;
            j -= 32;
        }
        if (t == 0) {
            atomicExch(&state[b], (2ULL << 32) | (unsigned)(prefix + total));
            sPrefix = prefix;
        }
    }
    __syncthreads();
    int pre = (b == 0) ? 0 : sPrefix;
    if (i < NN) {
        int rs = pre + s[t] - v;   // exclusive
        g_row[i] = rs;
        g_cur[i] = rs;
    }
    if (b == 0 && t == 0) g_row[NN] = EE;
}

// ---------------- k_place: 4 edges per thread ---------------------------------
__global__ void k_place(const int* __restrict__ ei, const float* __restrict__ w) {
    int t = blockIdx.x * blockDim.x + threadIdx.x;
    if (t >= EE / 4) return;
    int4 s = ((const int4*)ei)[t];
    int4 d = ((const int4*)(ei + EE))[t];
    float4 wv = ((const float4*)w)[t];
    float ds0 = g_deg[s.x], ds1 = g_deg[s.y], ds2 = g_deg[s.z], ds3 = g_deg[s.w];
    float dd0 = g_deg[d.x], dd1 = g_deg[d.y], dd2 = g_deg[d.z], dd3 = g_deg[d.w];
    float c0 = -((ds0 > 0.f ? rsqrtf(ds0) : 0.f) * wv.x * (dd0 > 0.f ? rsqrtf(dd0) : 0.f));
    float c1 = -((ds1 > 0.f ? rsqrtf(ds1) : 0.f) * wv.y * (dd1 > 0.f ? rsqrtf(dd1) : 0.f));
    float c2 = -((ds2 > 0.f ? rsqrtf(ds2) : 0.f) * wv.z * (dd2 > 0.f ? rsqrtf(dd2) : 0.f));
    float c3 = -((ds3 > 0.f ? rsqrtf(ds3) : 0.f) * wv.w * (dd3 > 0.f ? rsqrtf(dd3) : 0.f));
    int p0 = atomicAdd(&g_cur[d.x], 1);
    int p1 = atomicAdd(&g_cur[d.y], 1);
    int p2 = atomicAdd(&g_cur[d.z], 1);
    int p3 = atomicAdd(&g_cur[d.w], 1);
    g_csr[p0] = make_int2(s.x, __float_as_int(c0));
    g_csr[p1] = make_int2(s.y, __float_as_int(c1));
    g_csr[p2] = make_int2(s.z, __float_as_int(c2));
    g_csr[p3] = make_int2(s.w, __float_as_int(c3));
}

// ---------------- gathers (unroll 8 for MLP) -----------------------------------
__device__ __forceinline__ void gather2(int node, int lane,
                                        const float* __restrict__ a,
                                        const float* __restrict__ b,
                                        float& ra, float& rb) {
    int beg = g_row[node], end = g_row[node + 1];
    float sa = 0.0f, sb = 0.0f;
    int e = beg;
    for (; e + 8 <= end; e += 8) {
        int2 t0 = g_csr[e],     t1 = g_csr[e + 1], t2 = g_csr[e + 2], t3 = g_csr[e + 3];
        int2 t4 = g_csr[e + 4], t5 = g_csr[e + 5], t6 = g_csr[e + 6], t7 = g_csr[e + 7];
        float a0 = a[t0.x * CC + lane], a1 = a[t1.x * CC + lane];
        float a2 = a[t2.x * CC + lane], a3 = a[t3.x * CC + lane];
        float a4 = a[t4.x * CC + lane], a5 = a[t5.x * CC + lane];
        float a6 = a[t6.x * CC + lane], a7 = a[t7.x * CC + lane];
        float b0 = b[t0.x * CC + lane], b1 = b[t1.x * CC + lane];
        float b2 = b[t2.x * CC + lane], b3 = b[t3.x * CC + lane];
        float b4 = b[t4.x * CC + lane], b5 = b[t5.x * CC + lane];
        float b6 = b[t6.x * CC + lane], b7 = b[t7.x * CC + lane];
        sa += __int_as_float(t0.y) * a0 + __int_as_float(t1.y) * a1
            + __int_as_float(t2.y) * a2 + __int_as_float(t3.y) * a3
            + __int_as_float(t4.y) * a4 + __int_as_float(t5.y) * a5
            + __int_as_float(t6.y) * a6 + __int_as_float(t7.y) * a7;
        sb += __int_as_float(t0.y) * b0 + __int_as_float(t1.y) * b1
            + __int_as_float(t2.y) * b2 + __int_as_float(t3.y) * b3
            + __int_as_float(t4.y) * b4 + __int_as_float(t5.y) * b5
            + __int_as_float(t6.y) * b6 + __int_as_float(t7.y) * b7;
    }
    for (; e < end; e++) {
        int2 t = g_csr[e];
        float c = __int_as_float(t.y);
        sa += c * a[t.x * CC + lane];
        sb += c * b[t.x * CC + lane];
    }
    ra = sa; rb = sb;
}

__device__ __forceinline__ void gather1(int node, int lane,
                                        const float* __restrict__ a, float& ra) {
    int beg = g_row[node], end = g_row[node + 1];
    float sa = 0.0f;
    int e = beg;
    for (; e + 8 <= end; e += 8) {
        int2 t0 = g_csr[e],     t1 = g_csr[e + 1], t2 = g_csr[e + 2], t3 = g_csr[e + 3];
        int2 t4 = g_csr[e + 4], t5 = g_csr[e + 5], t6 = g_csr[e + 6], t7 = g_csr[e + 7];
        float a0 = a[t0.x * CC + lane], a1 = a[t1.x * CC + lane];
        float a2 = a[t2.x * CC + lane], a3 = a[t3.x * CC + lane];
        float a4 = a[t4.x * CC + lane], a5 = a[t5.x * CC + lane];
        float a6 = a[t6.x * CC + lane], a7 = a[t7.x * CC + lane];
        sa += __int_as_float(t0.y) * a0 + __int_as_float(t1.y) * a1
            + __int_as_float(t2.y) * a2 + __int_as_float(t3.y) * a3
            + __int_as_float(t4.y) * a4 + __int_as_float(t5.y) * a5
            + __int_as_float(t6.y) * a6 + __int_as_float(t7.y) * a7;
    }
    for (; e < end; e++) {
        int2 t = g_csr[e];
        sa += __int_as_float(t.y) * a[t.x * CC + lane];
    }
    ra = sa;
}

// ---------------- k_gates: gather(x,h) + gates z,r + px2 (4 nodes/warp) -------
// R5 structure (4 nodes, fully-unrolled staging, grid 592) with k-pair weight
// packing: every fma2 reads (w_k, w_k+1) from smem and a natural (s_k, s_k+1)
// register pair out of an LDS.128 -> zero MOV overhead.
__global__ void __launch_bounds__(256) k_gates(
        const float* __restrict__ x, const float* __restrict__ h,
        const float* __restrict__ Wx, const float* __restrict__ bx,
        const float* __restrict__ Wh, const float* __restrict__ bh) {
    extern __shared__ float2 dynw[];
    float2* sZ0 = dynw;            // z: Wx[0,0] k-pairs
    float2* sZ1 = dynw + 512;      // z: Wx[0,1]
    float2* sZ2 = dynw + 1024;     // z: Wh[0,0]
    float2* sZ3 = dynw + 1536;     // z: Wh[0,1]
    float2* sR0 = dynw + 2048;     // r: Wx[1,0]
    float2* sR1 = dynw + 2560;     // r: Wx[1,1]
    float2* sR2 = dynw + 3072;     // r: Wh[1,0]
    float2* sR3 = dynw + 3584;     // r: Wh[1,1]
    float2* sP0 = dynw + 4096;     // px2: Wx[2,0]
    float2* sP1 = dynw + 4608;     // px2: Wx[2,1]
    __shared__ __align__(16) float sIn[8 * 4 * 4 * 32];  // 16KB

    int tid = threadIdx.x;
    for (int i = tid; i < 512; i += blockDim.x) {
        int t = i >> 5, c = i & 31;
        int o = t * 64 + c;
        sZ0[i] = make_float2(Wx[o],        Wx[o + 32]);
        sZ1[i] = make_float2(Wx[1024 + o], Wx[1024 + o + 32]);
        sZ2[i] = make_float2(Wh[o],        Wh[o + 32]);
        sZ3[i] = make_float2(Wh[1024 + o], Wh[1024 + o + 32]);
        sR0[i] = make_float2(Wx[2048 + o], Wx[2048 + o + 32]);
        sR1[i] = make_float2(Wx[3072 + o], Wx[3072 + o + 32]);
        sR2[i] = make_float2(Wh[2048 + o], Wh[2048 + o + 32]);
        sR3[i] = make_float2(Wh[3072 + o], Wh[3072 + o + 32]);
        sP0[i] = make_float2(Wx[4096 + o], Wx[4096 + o + 32]);
        sP1[i] = make_float2(Wx[5120 + o], Wx[5120 + o + 32]);
    }
    __syncthreads();

    int lane = tid & 31;
    int warp = tid >> 5;
    float bz = bx[lane] + bh[lane];
    float br = bx[32 + lane] + bh[32 + lane];
    float b2 = bx[64 + lane] + bh[64 + lane];

    int gw = blockIdx.x * 8 + warp;
    int stride = gridDim.x * 8 * 4;
    float* stage = &sIn[warp * 512];

    for (int nb = gw * 4; nb < NN; nb += stride) {
        float hv[4];
        // ---- gather phase (fully unrolled: cross-node LDG MLP) ----
#pragma unroll
        for (int i = 0; i < 4; i++) {
            int node = nb + i;
            float xv = 0.f, hvv = 0.f, ax = 0.f, ah = 0.f;
            if (node < NN) {
                int base = node * CC + lane;
                xv = x[base];
                hvv = h[base];
                gather2(node, lane, x, h, ax, ah);
            }
            hv[i] = hvv;
            stage[i * 128 +  0 + lane] = xv;
            stage[i * 128 + 32 + lane] = ax;
            stage[i * 128 + 64 + lane] = hvv;
            stage[i * 128 + 96 + lane] = ah;
        }
        __syncwarp();

        unsigned long long accz[4], accr[4], accp[4];
#pragma unroll
        for (int i = 0; i < 4; i++) {
            accz[i] = pack2(bz, 0.f);
            accr[i] = pack2(br, 0.f);
            accp[i] = pack2(b2, 0.f);
        }
        const float4* st4 = (const float4*)stage;

#pragma unroll 1
        for (int q = 0; q < 8; q++) {
            int r0 = (2 * q) * 32 + lane, r1 = (2 * q + 1) * 32 + lane;
            float2 z0a = sZ0[r0], z0b = sZ0[r1], z1a = sZ1[r0], z1b = sZ1[r1];
            float2 z2a = sZ2[r0], z2b = sZ2[r1], z3a = sZ3[r0], z3b = sZ3[r1];
            float2 q0a = sR0[r0], q0b = sR0[r1], q1a = sR1[r0], q1b = sR1[r1];
            float2 q2a = sR2[r0], q2b = sR2[r1], q3a = sR3[r0], q3b = sR3[r1];
            float2 p0a = sP0[r0], p0b = sP0[r1], p1a = sP1[r0], p1b = sP1[r1];
#pragma unroll
            for (int i = 0; i < 4; i++) {
                float4 vx = st4[i * 32 +  0 + q];
                float4 va = st4[i * 32 +  8 + q];
                float4 vh = st4[i * 32 + 16 + q];
                float4 vr = st4[i * 32 + 24 + q];
                fma2(accz[i], z0a, vx.x, vx.y); fma2(accz[i], z0b, vx.z, vx.w);
                fma2(accz[i], z1a, va.x, va.y); fma2(accz[i], z1b, va.z, va.w);
                fma2(accz[i], z2a, vh.x, vh.y); fma2(accz[i], z2b, vh.z, vh.w);
                fma2(accz[i], z3a, vr.x, vr.y); fma2(accz[i], z3b, vr.z, vr.w);
                fma2(accr[i], q0a, vx.x, vx.y); fma2(accr[i], q0b, vx.z, vx.w);
                fma2(accr[i], q1a, va.x, va.y); fma2(accr[i], q1b, va.z, va.w);
                fma2(accr[i], q2a, vh.x, vh.y); fma2(accr[i], q2b, vh.z, vh.w);
                fma2(accr[i], q3a, vr.x, vr.y); fma2(accr[i], q3b, vr.z, vr.w);
                fma2(accp[i], p0a, vx.x, vx.y); fma2(accp[i], p0b, vx.z, vx.w);
                fma2(accp[i], p1a, va.x, va.y); fma2(accp[i], p1b, va.z, va.w);
            }
        }

#pragma unroll
        for (int i = 0; i < 4; i++) {
            int node = nb + i;
            if (node >= NN) break;
            float2 az = unpack2(accz[i]);
            float2 ar = unpack2(accr[i]);
            float2 ap = unpack2(accp[i]);
            float z = 1.0f / (1.0f + __expf(-(az.x + az.y)));
            float r = 1.0f / (1.0f + __expf(-(ar.x + ar.y)));
            int base = node * CC + lane;
            g_z[base] = z;
            g_hr[base] = hv[i] * r;
            g_px2[base] = ap.x + ap.y;
        }
        __syncwarp();
    }
}

// ---------------- k_final: gather(hr) + h_tilde + h_new + head (8 nodes/warp) -
__global__ void __launch_bounds__(256) k_final(
        const float* __restrict__ h,
        const float* __restrict__ Wh,
        const float* __restrict__ Wl, const float* __restrict__ bl,
        float* __restrict__ out) {
    extern __shared__ float2 dynw[];
    float2* sQ0 = dynw;          // Wh[2,0] k-pairs
    float2* sQ1 = dynw + 512;    // Wh[2,1] k-pairs
    __shared__ __align__(16) float sIn[8 * 8 * 2 * 32];
    __shared__ float sWl[32];

    int tid = threadIdx.x;
    for (int i = tid; i < 512; i += blockDim.x) {
        int t = i >> 5, c = i & 31;
        int o = t * 64 + c;
        sQ0[i] = make_float2(Wh[4096 + o], Wh[4096 + o + 32]);
        sQ1[i] = make_float2(Wh[5120 + o], Wh[5120 + o + 32]);
    }
    if (tid < 32) sWl[tid] = Wl[tid];
    __syncthreads();

    int lane = tid & 31;
    int warp = tid >> 5;
    float blv = bl[0];

    int gw = blockIdx.x * 8 + warp;
    int stride = gridDim.x * 8 * 8;
    float* stage = &sIn[warp * 512];

    for (int nb = gw * 8; nb < NN; nb += stride) {
        float px2r[8];
#pragma unroll
        for (int i = 0; i < 8; i++) {
            int node = nb + i;
            float hrv = 0.f, ahr = 0.f, px = 0.f;
            if (node < NN) {
                int base = node * CC + lane;
                hrv = g_hr[base];
                px = g_px2[base];
                gather1(node, lane, g_hr, ahr);
            }
            px2r[i] = px;
            stage[i * 64 +  0 + lane] = hrv;
            stage[i * 64 + 32 + lane] = ahr;
        }
        __syncwarp();

        unsigned long long acc[8];
#pragma unroll
        for (int i = 0; i < 8; i++) acc[i] = pack2(px2r[i], 0.f);
        const float4* st4 = (const float4*)stage;

#pragma unroll 1
        for (int q = 0; q < 8; q++) {
            int r0 = (2 * q) * 32 + lane, r1 = (2 * q + 1) * 32 + lane;
            float2 w0a = sQ0[r0], w0b = sQ0[r1];
            float2 w1a = sQ1[r0], w1b = sQ1[r1];
#pragma unroll
            for (int i = 0; i < 8; i++) {
                float4 vh = st4[i * 16 + 0 + q];
                float4 vr = st4[i * 16 + 8 + q];
                fma2(acc[i], w0a, vh.x, vh.y); fma2(acc[i], w0b, vh.z, vh.w);
                fma2(acc[i], w1a, vr.x, vr.y); fma2(acc[i], w1b, vr.z, vr.w);
            }
        }

#pragma unroll
        for (int i = 0; i < 8; i++) {
            int node = nb + i;
            if (node >= NN) break;
            float2 a2 = unpack2(acc[i]);
            float ht = tanhf(a2.x + a2.y);
            int base = node * CC + lane;
            float zv = g_z[base];
            float hvv = h[base];
            float hn = zv * hvv + (1.0f - zv) * ht;

            out[NN + base] = hn;

            float rl = fmaxf(hn, 0.0f) * sWl[lane];
#pragma unroll
            for (int off = 16; off > 0; off >>= 1)
                rl += __shfl_xor_sync(0xffffffffu, rl, off);
            if (lane == 0) {
                float s = rl + blv;
                out[node] = log1pf(__expf(-fabsf(s))) + fmaxf(s, 0.0f);
            }
        }
        __syncwarp();
    }
}

// ---------------- launch ------------------------------------------------------
extern "C" void kernel_launch(void* const* d_in, const int* in_sizes, int n_in,
                              void* d_out, int out_size) {
    const float* x  = (const float*)d_in[0];
    const int*   ei = (const int*)d_in[1];
    const float* w  = (const float*)d_in[2];
    const float* h  = (const float*)d_in[3];
    const float* Wx = (const float*)d_in[4];
    const float* bx = (const float*)d_in[5];
    const float* Wh = (const float*)d_in[6];
    const float* bh = (const float*)d_in[7];
    const float* Wl = (const float*)d_in[8];
    const float* bl = (const float*)d_in[9];
    float* out = (float*)d_out;

    (void)in_sizes; (void)n_in; (void)out_size;

    cudaFuncSetAttribute(k_gates, cudaFuncAttributeMaxDynamicSharedMemorySize, 5120 * 8);
    cudaFuncSetAttribute(k_final, cudaFuncAttributeMaxDynamicSharedMemorySize, 1024 * 8);

    void* p_deg = nullptr; cudaGetSymbolAddress(&p_deg, g_deg);
    void* p_zb  = nullptr; cudaGetSymbolAddress(&p_zb, g_zbuf);
    cudaMemsetAsync(p_deg, 0, NN * sizeof(float));
    cudaMemsetAsync(p_zb, 0, (NN + 512) * sizeof(int));

    k_deg_hist<<<(EE / 4 + 255) / 256, 256>>>(ei, w);
    k_scan<<<NB, SCAN_T>>>();
    k_place<<<(EE / 4 + 255) / 256, 256>>>(ei, w);
    k_gates<<<592, 256, 5120 * 8>>>(x, h, Wx, bx, Wh, bh);
    k_final<<<592, 256, 1024 * 8>>>(h, Wh, Wl, bl, out);
}